// round 4
// baseline (speedup 1.0000x reference)
#include <cuda_runtime.h>

// Problem constants
#define A_N 64          // batch (number of paths per set)
#define T_N 128         // time steps
#define D_N 128         // feature dim
#define MM  127         // increments per path
#define NTRI 2080       // 64*65/2 upper-triangle pairs
#define NJOBS 8256      // 2080 (XX) + 2080 (YY) + 4096 (XY)
#define PAIR_STRIDE (MM * D_N)

// Dynamic smem partition (floats)
#define SM_M_F   (128 * 128)   // 16384 : M matrix (row 127 / col 127 are unused padding)
#define SM_A_F   (128 * 33)    //  4224 : dX chunk, padded pitch 33
#define SM_B_F   (128 * 33)    //  4224 : dY chunk
#define SM_K_F   (3 * 130)     //   390 : three PDE diagonals
#define SMEM_FLOATS (SM_M_F + SM_A_F + SM_B_F + SM_K_F)
#define SMEM_BYTES  (SMEM_FLOATS * 4)

// Scratch (static __device__ arrays: allocation-free per harness rules)
__device__ float g_dX[A_N * MM * D_N];
__device__ float g_dY[A_N * MM * D_N];
__device__ float g_res[NJOBS];

// ---------------------------------------------------------------------------
// Prologue: path increments dX = X[:,1:] - X[:,:-1], same for Y.
// ---------------------------------------------------------------------------
__global__ void sig_prep_kernel(const float* __restrict__ X,
                                const float* __restrict__ Y) {
    int idx = blockIdx.x * blockDim.x + threadIdx.x;
    const int total = A_N * MM * D_N;
    if (idx >= total) return;
    int a = idx / (MM * D_N);
    int r = idx - a * (MM * D_N);
    int i = r / D_N;
    int d = r - i * D_N;
    int g0 = a * T_N * D_N + i * D_N + d;
    g_dX[idx] = X[g0 + D_N] - X[g0];
    g_dY[idx] = Y[g0 + D_N] - Y[g0];
}

// ---------------------------------------------------------------------------
// Main: one CTA per (pair, gram) job.
//   Phase 1: M = dP * dQ^T  (127x127x128 fp32 GEMM, 8x8 register tiles)
//   Phase 2: anti-diagonal wavefront PDE:
//       K[i][j] = K[i][j-1] + K[i-1][j] + K[i-1][j-1]*(M[i-1][j-1]-1)
//   Result: weighted K[127][127] into g_res[job].
// ---------------------------------------------------------------------------
__global__ __launch_bounds__(256, 2) void sig_pair_kernel() {
    extern __shared__ float smem[];
    float* sM = smem;                       // [128][128]
    float* sA = smem + SM_M_F;              // [128][33]
    float* sB = sA + SM_A_F;                // [128][33]
    float* kbuf = sB + SM_B_F;              // 3 x 130

    const int job = blockIdx.x;
    const int tid = threadIdx.x;

    // --- decode job -> (P, Q, weight) ---
    const float* P;
    const float* Q;
    float w = 1.0f;
    if (job < 2 * NTRI) {
        const float* base = (job < NTRI) ? g_dX : g_dY;
        int t = (job < NTRI) ? job : (job - NTRI);
        int a = 0, rowlen = A_N;
        while (t >= rowlen) { t -= rowlen; rowlen--; a++; }
        int b = a + t;
        P = base + a * PAIR_STRIDE;
        Q = base + b * PAIR_STRIDE;
        w = (a == b) ? 1.0f : 2.0f;         // symmetric gram: off-diag counts twice
    } else {
        int t = job - 2 * NTRI;
        int a = t >> 6;
        int b = t & 63;
        P = g_dX + a * PAIR_STRIDE;
        Q = g_dY + b * PAIR_STRIDE;
    }

    // --- Phase 1: GEMM into sM ---
    const int tx = tid & 15;        // 0..15 (column group)
    const int ty = tid >> 4;        // 0..15 (row group)
    const int lane = tid & 31;
    const int wrp = tid >> 5;

    float acc[8][8];
#pragma unroll
    for (int ii = 0; ii < 8; ii++)
#pragma unroll
        for (int jj = 0; jj < 8; jj++) acc[ii][jj] = 0.0f;

    // zero the padding row 127 once (covered by the first in-loop barrier)
    if (tid < 33) { sA[127 * 33 + tid] = 0.0f; sB[127 * 33 + tid] = 0.0f; }

    for (int kc = 0; kc < D_N; kc += 32) {
        __syncthreads();   // previous chunk consumed (also covers the init above)
        // coalesced loads: lane = d within chunk, rows strided by 8 warps
        for (int i = wrp; i < MM; i += 8) {
            sA[i * 33 + lane] = P[i * D_N + kc + lane];
            sB[i * 33 + lane] = Q[i * D_N + kc + lane];
        }
        __syncthreads();
#pragma unroll 8
        for (int d = 0; d < 32; d++) {
            float av[8], bv[8];
#pragma unroll
            for (int ii = 0; ii < 8; ii++) av[ii] = sA[(ty + 16 * ii) * 33 + d];
#pragma unroll
            for (int jj = 0; jj < 8; jj++) bv[jj] = sB[(tx + 16 * jj) * 33 + d];
#pragma unroll
            for (int ii = 0; ii < 8; ii++)
#pragma unroll
                for (int jj = 0; jj < 8; jj++)
                    acc[ii][jj] += av[ii] * bv[jj];
        }
    }
    __syncthreads();
#pragma unroll
    for (int ii = 0; ii < 8; ii++)
#pragma unroll
        for (int jj = 0; jj < 8; jj++)
            sM[(ty + 16 * ii) * 128 + (tx + 16 * jj)] = acc[ii][jj];

    // --- Phase 2: wavefront PDE ---
    float* K2 = kbuf;               // diagonal d-2
    float* K1 = kbuf + 130;         // diagonal d-1
    float* Kc = kbuf + 260;         // diagonal d
    if (tid < 128) { K2[tid] = 1.0f; K1[tid] = 1.0f; }  // boundaries K[0][*]=K[*][0]=1
    __syncthreads();

    for (int dg = 2; dg <= 254; dg++) {
        if (tid < 127) {
            int i = tid + 1;
            int j = dg - i;
            if (j >= 1 && j <= 127) {
                float m = sM[(i - 1) * 128 + (j - 1)];
                Kc[i] = K1[i] + K1[i - 1] + K2[i - 1] * (m - 1.0f);
            }
        } else if (tid == 127) {
            if (dg <= 127) Kc[0] = 1.0f;        // boundary cell (0, dg)
        } else if (tid == 128) {
            if (dg <= 127) Kc[dg] = 1.0f;       // boundary cell (dg, 0)
        }
        __syncthreads();
        float* tmp = K2; K2 = K1; K1 = Kc; Kc = tmp;
    }

    if (tid == 0) g_res[job] = w * K1[127];     // K[127][127], weighted
}

// ---------------------------------------------------------------------------
// Deterministic reduction: mmd = mean(KXX) + mean(KYY) - 2*mean(KXY)
// ---------------------------------------------------------------------------
__global__ void sig_finalize_kernel(float* __restrict__ out) {
    __shared__ double sh0[256], sh1[256], sh2[256];
    int tid = threadIdx.x;
    double xx = 0.0, yy = 0.0, xy = 0.0;
    for (int idx = tid; idx < NJOBS; idx += 256) {
        double v = (double)g_res[idx];
        if (idx < NTRI) xx += v;
        else if (idx < 2 * NTRI) yy += v;
        else xy += v;
    }
    sh0[tid] = xx; sh1[tid] = yy; sh2[tid] = xy;
    __syncthreads();
    for (int s = 128; s > 0; s >>= 1) {
        if (tid < s) {
            sh0[tid] += sh0[tid + s];
            sh1[tid] += sh1[tid + s];
            sh2[tid] += sh2[tid + s];
        }
        __syncthreads();
    }
    if (tid == 0) {
        double m = sh0[0] / 4096.0 + sh1[0] / 4096.0 - 2.0 * sh2[0] / 4096.0;
        out[0] = (float)m;
    }
}

// ---------------------------------------------------------------------------
extern "C" void kernel_launch(void* const* d_in, const int* in_sizes, int n_in,
                              void* d_out, int out_size) {
    (void)in_sizes; (void)n_in; (void)out_size;
    const float* X = (const float*)d_in[0];
    const float* Y = (const float*)d_in[1];
    float* out = (float*)d_out;

    cudaFuncSetAttribute(sig_pair_kernel,
                         cudaFuncAttributeMaxDynamicSharedMemorySize, SMEM_BYTES);

    const int total = A_N * MM * D_N;
    sig_prep_kernel<<<(total + 255) / 256, 256>>>(X, Y);
    sig_pair_kernel<<<NJOBS, 256, SMEM_BYTES>>>();
    sig_finalize_kernel<<<1, 256>>>(out);
}

// round 10
// speedup vs baseline: 1.5447x; 1.5447x over previous
#include <cuda_runtime.h>
#include <cuda_bf16.h>
#include <cstdint>

// ---------------------------------------------------------------------------
// Problem constants
// ---------------------------------------------------------------------------
#define A_N 64          // batch per set
#define T_N 128         // time steps
#define D_N 128         // feature dim
#define MM  127         // increments per path
#define NTRI 2080       // 64*65/2 upper-triangle pairs
#define NJOBS 8256      // 2080 (XX) + 2080 (YY) + 4096 (XY)
#define NPATH 128       // 64 X paths + 64 Y paths

// Fragment-permuted storage: per path 8 k16-chunks x 16 r8-groups x 32 lanes
// x 2 subs x 4B  = 32KB  (8192 uint32 granules per path)
#define GR_PER_PATH 8192

// Smem layout (floats): M matrix 128 x 132  +  3 PDE diagonals of 132
#define M_STRIDE  132
#define M_FLOATS  (128 * M_STRIDE)            // 16896
#define KB_FLOATS (3 * M_STRIDE)              // 396
#define SMEM_DYN  ((M_FLOATS + KB_FLOATS) * 4)  // 69168 bytes

// ---------------------------------------------------------------------------
// Scratch (static __device__ arrays: allocation-free per harness rules)
// ---------------------------------------------------------------------------
__device__ __align__(16) unsigned int g_fragH[NPATH * GR_PER_PATH];  // bf16 hi, 4MB
__device__ __align__(16) unsigned int g_fragL[NPATH * GR_PER_PATH];  // bf16 lo, 4MB
__device__ float g_res[NJOBS];

// ---------------------------------------------------------------------------
// Warp mma: m16n8k16 row.col f32.bf16.bf16.f32  (HMMA, legal at compute_103)
// a regs: {a0h.x (row g,k 2tc..), a1h.x (row g+8), a0h.y (k+8), a1h.y}
// b regs: {b.x (k 2tc.., col g), b.y (k+8)}
// ---------------------------------------------------------------------------
__device__ __forceinline__ void mma_bf16(float* d, uint2 a0, uint2 a1, uint2 b) {
    asm volatile(
        "mma.sync.aligned.m16n8k16.row.col.f32.bf16.bf16.f32 "
        "{%0,%1,%2,%3}, {%4,%5,%6,%7}, {%8,%9}, {%0,%1,%2,%3};"
        : "+f"(d[0]), "+f"(d[1]), "+f"(d[2]), "+f"(d[3])
        : "r"(a0.x), "r"(a1.x), "r"(a0.y), "r"(a1.y), "r"(b.x), "r"(b.y));
}

// granule-pair index (uint2 units): ((path*8 + k16)*16 + r8)*32 + lane
__device__ __forceinline__ int gidx(int path, int k16, int r8, int lane) {
    return ((path * 8 + k16) * 16 + r8) * 32 + lane;
}

// ---------------------------------------------------------------------------
// Prologue: increments dZ = Z[:,1:]-Z[:,:-1] (row 127 zero-padded), split
// into bf16 hi + bf16 lo, stored directly in mma-fragment-permuted layout.
// One thread per 4B output granule (2 adjacent k elements) -> coalesced.
// ---------------------------------------------------------------------------
__global__ void sig_prep_kernel(const float* __restrict__ X,
                                const float* __restrict__ Y) {
    int t = blockIdx.x * blockDim.x + threadIdx.x;
    if (t >= NPATH * GR_PER_PATH) return;
    int path = t >> 13;                 // /8192
    int rem  = t & 8191;
    int k16  = rem >> 10;
    int rem2 = rem & 1023;
    int r8   = rem2 >> 6;
    int rem3 = rem2 & 63;
    int lane = rem3 >> 1;
    int sub  = rem3 & 1;
    int g  = lane >> 2;
    int tc = lane & 3;
    int r  = r8 * 8 + g;
    int k  = k16 * 16 + sub * 8 + tc * 2;

    float d0 = 0.0f, d1 = 0.0f;
    if (r < MM) {
        const float* src = (path < A_N) ? (X + path * T_N * D_N)
                                        : (Y + (path - A_N) * T_N * D_N);
        const float* p0 = src + r * D_N + k;
        d0 = p0[D_N] - p0[0];
        d1 = p0[D_N + 1] - p0[1];
    }
    __nv_bfloat16 h0 = __float2bfloat16(d0);
    __nv_bfloat16 h1 = __float2bfloat16(d1);
    __nv_bfloat16 l0 = __float2bfloat16(d0 - __bfloat162float(h0));
    __nv_bfloat16 l1 = __float2bfloat16(d1 - __bfloat162float(h1));
    unsigned int hp = ((unsigned int)__bfloat16_as_ushort(h1) << 16) |
                       (unsigned int)__bfloat16_as_ushort(h0);
    unsigned int lp = ((unsigned int)__bfloat16_as_ushort(l1) << 16) |
                       (unsigned int)__bfloat16_as_ushort(l0);
    g_fragH[t] = hp;
    g_fragL[t] = lp;
}

// ---------------------------------------------------------------------------
// Main: one CTA (256 threads, 8 warps) per job.
//   Phase 1: M = P.Q^T via mma.sync bf16 3-pass split (hh+hl+lh), fp32 accum.
//            Two 64x128 halves; warp grid 2x4, warp tile 32x32 (32 accs/thr).
//            Fragments loaded straight from permuted gmem (L1/L2-hot LDG.64).
//   Phase 2: 253-step anti-diagonal wavefront PDE (proven correct).
// ---------------------------------------------------------------------------
__global__ __launch_bounds__(256, 3) void sig_pair_kernel() {
    extern __shared__ float smem[];
    float* sM = smem;
    float* kbase = smem + M_FLOATS;

    const int job = blockIdx.x;
    const int tid = threadIdx.x;
    const int lane = tid & 31;
    const int wid = tid >> 5;
    const int wm = wid >> 2;    // 0..1 (m-block within half)
    const int wn = wid & 3;     // 0..3 (n-block)

    // --- decode job -> (p, q path indices, weight) ---
    int p, q;
    float w = 1.0f;
    if (job < 2 * NTRI) {
        bool isY = job >= NTRI;
        int t = isY ? job - NTRI : job;
        int a = 0, rl = A_N;
        while (t >= rl) { t -= rl; rl--; a++; }
        int b = a + t;
        int off = isY ? A_N : 0;
        p = a + off;
        q = b + off;
        w = (a == b) ? 1.0f : 2.0f;     // symmetric gram: off-diag twice
    } else {
        int t = job - 2 * NTRI;
        p = (t >> 6);                   // X path
        q = A_N + (t & 63);             // Y path
    }

    const uint2* __restrict__ FH = (const uint2*)g_fragH;
    const uint2* __restrict__ FL = (const uint2*)g_fragL;

    // --- Phase 1: GEMM, two 64-row halves ---
    const int g8 = lane >> 2;
    const int tc = lane & 3;
#pragma unroll
    for (int h = 0; h < 2; h++) {
        float acc[2][4][4];
#pragma unroll
        for (int ms = 0; ms < 2; ms++)
#pragma unroll
            for (int ns = 0; ns < 4; ns++)
#pragma unroll
                for (int c = 0; c < 4; c++) acc[ms][ns][c] = 0.0f;

        const int r8base = 8 * h + 4 * wm;
#pragma unroll
        for (int k16 = 0; k16 < 8; k16++) {
            uint2 aH[2][2], aL[2][2];
#pragma unroll
            for (int ms = 0; ms < 2; ms++) {
                int r8 = r8base + 2 * ms;
                aH[ms][0] = FH[gidx(p, k16, r8, lane)];
                aH[ms][1] = FH[gidx(p, k16, r8 + 1, lane)];
                aL[ms][0] = FL[gidx(p, k16, r8, lane)];
                aL[ms][1] = FL[gidx(p, k16, r8 + 1, lane)];
            }
#pragma unroll
            for (int ns = 0; ns < 4; ns++) {
                int j8 = 4 * wn + ns;
                uint2 bH = FH[gidx(q, k16, j8, lane)];
                uint2 bL = FL[gidx(q, k16, j8, lane)];
#pragma unroll
                for (int ms = 0; ms < 2; ms++) {
                    mma_bf16(acc[ms][ns], aH[ms][0], aH[ms][1], bH);  // hi*hi
                    mma_bf16(acc[ms][ns], aH[ms][0], aH[ms][1], bL);  // hi*lo
                    mma_bf16(acc[ms][ns], aL[ms][0], aL[ms][1], bH);  // lo*hi
                }
            }
        }
        // store C fragments to sM: c0,c1 -> (row g, col 2tc..), c2,c3 -> row g+8
#pragma unroll
        for (int ms = 0; ms < 2; ms++) {
            int row0 = 64 * h + 32 * wm + 16 * ms + g8;
#pragma unroll
            for (int ns = 0; ns < 4; ns++) {
                int col = 32 * wn + 8 * ns + 2 * tc;
                *(float2*)&sM[row0 * M_STRIDE + col] =
                    make_float2(acc[ms][ns][0], acc[ms][ns][1]);
                *(float2*)&sM[(row0 + 8) * M_STRIDE + col] =
                    make_float2(acc[ms][ns][2], acc[ms][ns][3]);
            }
        }
    }

    // --- Phase 2: wavefront PDE ---
    float* K2 = kbase;                  // diagonal d-2
    float* K1 = kbase + M_STRIDE;       // diagonal d-1
    float* Kc = kbase + 2 * M_STRIDE;   // diagonal d
    if (tid < 128) { K2[tid] = 1.0f; K1[tid] = 1.0f; }
    __syncthreads();

    for (int dg = 2; dg <= 254; dg++) {
        if (tid < 127) {
            int i = tid + 1;
            int j = dg - i;
            if (j >= 1 && j <= 127) {
                float m = sM[(i - 1) * M_STRIDE + (j - 1)];
                Kc[i] = K1[i] + K1[i - 1] + K2[i - 1] * (m - 1.0f);
            }
        } else if (tid == 127) {
            if (dg <= 127) Kc[0] = 1.0f;
        } else if (tid == 128) {
            if (dg <= 127) Kc[dg] = 1.0f;
        }
        __syncthreads();
        float* tmp = K2; K2 = K1; K1 = Kc; Kc = tmp;
    }

    if (tid == 0) g_res[job] = w * K1[127];     // K[127][127], weighted
}

// ---------------------------------------------------------------------------
// Deterministic reduction: mmd = mean(KXX) + mean(KYY) - 2*mean(KXY)
// ---------------------------------------------------------------------------
__global__ void sig_finalize_kernel(float* __restrict__ out) {
    __shared__ double sh0[256], sh1[256], sh2[256];
    int tid = threadIdx.x;
    double xx = 0.0, yy = 0.0, xy = 0.0;
    for (int idx = tid; idx < NJOBS; idx += 256) {
        double v = (double)g_res[idx];
        if (idx < NTRI) xx += v;
        else if (idx < 2 * NTRI) yy += v;
        else xy += v;
    }
    sh0[tid] = xx; sh1[tid] = yy; sh2[tid] = xy;
    __syncthreads();
    for (int s = 128; s > 0; s >>= 1) {
        if (tid < s) {
            sh0[tid] += sh0[tid + s];
            sh1[tid] += sh1[tid + s];
            sh2[tid] += sh2[tid + s];
        }
        __syncthreads();
    }
    if (tid == 0) {
        double m = sh0[0] / 4096.0 + sh1[0] / 4096.0 - 2.0 * sh2[0] / 4096.0;
        out[0] = (float)m;
    }
}

// ---------------------------------------------------------------------------
extern "C" void kernel_launch(void* const* d_in, const int* in_sizes, int n_in,
                              void* d_out, int out_size) {
    (void)in_sizes; (void)n_in; (void)out_size;
    const float* X = (const float*)d_in[0];
    const float* Y = (const float*)d_in[1];
    float* out = (float*)d_out;

    cudaFuncSetAttribute(sig_pair_kernel,
                         cudaFuncAttributeMaxDynamicSharedMemorySize, SMEM_DYN);

    const int ngr = NPATH * GR_PER_PATH;
    sig_prep_kernel<<<(ngr + 255) / 256, 256>>>(X, Y);
    sig_pair_kernel<<<NJOBS, 256, SMEM_DYN>>>();
    sig_finalize_kernel<<<1, 256>>>(out);
}

// round 11
// speedup vs baseline: 2.4018x; 1.5549x over previous
#include <cuda_runtime.h>
#include <cuda_bf16.h>
#include <cstdint>

// ---------------------------------------------------------------------------
// Problem constants
// ---------------------------------------------------------------------------
#define A_N 64          // batch per set
#define T_N 128         // time steps
#define D_N 128         // feature dim
#define MM  127         // increments per path
#define NTRI 2080       // 64*65/2 upper-triangle pairs
#define NJOBS 8256      // 2080 (XX) + 2080 (YY) + 4096 (XY)
#define NPATH 128       // 64 X paths + 64 Y paths

// Fragment-permuted storage: per path 8 k16-chunks x 16 r8-groups x 32 lanes
// x 2 subs x 4B  = 32KB  (8192 uint32 granules per path)
#define GR_PER_PATH 8192

// Smem: M' = (M - 1) matrix, 128 x 132 floats (stride 132 -> tolerable PDE
// bank pattern, float2-aligned epilogue stores). No diagonal buffers needed:
// the PDE is register-resident in one warp.
#define M_STRIDE  132
#define M_FLOATS  (128 * M_STRIDE)            // 16896
#define SMEM_DYN  (M_FLOATS * 4)              // 67584 bytes -> 3 CTAs/SM

// ---------------------------------------------------------------------------
// Scratch (static __device__ arrays: allocation-free per harness rules)
// ---------------------------------------------------------------------------
__device__ __align__(16) unsigned int g_fragH[NPATH * GR_PER_PATH];  // bf16 hi
__device__ __align__(16) unsigned int g_fragL[NPATH * GR_PER_PATH];  // bf16 lo
__device__ float g_res[NJOBS];

// ---------------------------------------------------------------------------
// Warp mma: m16n8k16 row.col f32.bf16.bf16.f32  (HMMA, legal at compute_103)
// ---------------------------------------------------------------------------
__device__ __forceinline__ void mma_bf16(float* d, uint2 a0, uint2 a1, uint2 b) {
    asm volatile(
        "mma.sync.aligned.m16n8k16.row.col.f32.bf16.bf16.f32 "
        "{%0,%1,%2,%3}, {%4,%5,%6,%7}, {%8,%9}, {%0,%1,%2,%3};"
        : "+f"(d[0]), "+f"(d[1]), "+f"(d[2]), "+f"(d[3])
        : "r"(a0.x), "r"(a1.x), "r"(a0.y), "r"(a1.y), "r"(b.x), "r"(b.y));
}

// granule-pair index (uint2 units): ((path*8 + k16)*16 + r8)*32 + lane
__device__ __forceinline__ int gidx(int path, int k16, int r8, int lane) {
    return ((path * 8 + k16) * 16 + r8) * 32 + lane;
}

// ---------------------------------------------------------------------------
// Prologue: increments dZ = Z[:,1:]-Z[:,:-1] (row 127 zero-padded), split
// into bf16 hi + bf16 lo, stored directly in mma-fragment-permuted layout.
// ---------------------------------------------------------------------------
__global__ void sig_prep_kernel(const float* __restrict__ X,
                                const float* __restrict__ Y) {
    int t = blockIdx.x * blockDim.x + threadIdx.x;
    if (t >= NPATH * GR_PER_PATH) return;
    int path = t >> 13;                 // /8192
    int rem  = t & 8191;
    int k16  = rem >> 10;
    int rem2 = rem & 1023;
    int r8   = rem2 >> 6;
    int rem3 = rem2 & 63;
    int lane = rem3 >> 1;
    int sub  = rem3 & 1;
    int g  = lane >> 2;
    int tc = lane & 3;
    int r  = r8 * 8 + g;
    int k  = k16 * 16 + sub * 8 + tc * 2;

    float d0 = 0.0f, d1 = 0.0f;
    if (r < MM) {
        const float* src = (path < A_N) ? (X + path * T_N * D_N)
                                        : (Y + (path - A_N) * T_N * D_N);
        const float* p0 = src + r * D_N + k;
        d0 = p0[D_N] - p0[0];
        d1 = p0[D_N + 1] - p0[1];
    }
    __nv_bfloat16 h0 = __float2bfloat16(d0);
    __nv_bfloat16 h1 = __float2bfloat16(d1);
    __nv_bfloat16 l0 = __float2bfloat16(d0 - __bfloat162float(h0));
    __nv_bfloat16 l1 = __float2bfloat16(d1 - __bfloat162float(h1));
    unsigned int hp = ((unsigned int)__bfloat16_as_ushort(h1) << 16) |
                       (unsigned int)__bfloat16_as_ushort(h0);
    unsigned int lp = ((unsigned int)__bfloat16_as_ushort(l1) << 16) |
                       (unsigned int)__bfloat16_as_ushort(l0);
    g_fragH[t] = hp;
    g_fragL[t] = lp;
}

// ---------------------------------------------------------------------------
// Main: one CTA (256 threads, 8 warps) per job.
//   Phase 1: M' = P.Q^T - 1 via mma.sync bf16 3-pass split, fp32 accum.
//   Phase 2: single-warp register-resident wavefront PDE (zero barriers):
//            lane L owns rows i = 4L+1 .. 4L+4; per anti-diagonal dg the
//            lane-above values arrive via shfl_up, M' via one LDS per row.
// ---------------------------------------------------------------------------
__global__ __launch_bounds__(256, 3) void sig_pair_kernel() {
    extern __shared__ float smem[];
    float* sM = smem;

    const int job = blockIdx.x;
    const int tid = threadIdx.x;
    const int lane = tid & 31;
    const int wid = tid >> 5;
    const int wm = wid >> 2;    // 0..1 (m-block within half)
    const int wn = wid & 3;     // 0..3 (n-block)

    // --- decode job -> (p, q path indices, weight) ---
    int p, q;
    float w = 1.0f;
    if (job < 2 * NTRI) {
        bool isY = job >= NTRI;
        int t = isY ? job - NTRI : job;
        int a = 0, rl = A_N;
        while (t >= rl) { t -= rl; rl--; a++; }
        int b = a + t;
        int off = isY ? A_N : 0;
        p = a + off;
        q = b + off;
        w = (a == b) ? 1.0f : 2.0f;     // symmetric gram: off-diag twice
    } else {
        int t = job - 2 * NTRI;
        p = (t >> 6);                   // X path
        q = A_N + (t & 63);             // Y path
    }

    const uint2* __restrict__ FH = (const uint2*)g_fragH;
    const uint2* __restrict__ FL = (const uint2*)g_fragL;

    // --- Phase 1: GEMM, two 64-row halves ---
    const int g8 = lane >> 2;
    const int tc = lane & 3;
#pragma unroll
    for (int h = 0; h < 2; h++) {
        float acc[2][4][4];
#pragma unroll
        for (int ms = 0; ms < 2; ms++)
#pragma unroll
            for (int ns = 0; ns < 4; ns++)
#pragma unroll
                for (int c = 0; c < 4; c++) acc[ms][ns][c] = 0.0f;

        const int r8base = 8 * h + 4 * wm;
#pragma unroll
        for (int k16 = 0; k16 < 8; k16++) {
            uint2 aH[2][2], aL[2][2];
#pragma unroll
            for (int ms = 0; ms < 2; ms++) {
                int r8 = r8base + 2 * ms;
                aH[ms][0] = FH[gidx(p, k16, r8, lane)];
                aH[ms][1] = FH[gidx(p, k16, r8 + 1, lane)];
                aL[ms][0] = FL[gidx(p, k16, r8, lane)];
                aL[ms][1] = FL[gidx(p, k16, r8 + 1, lane)];
            }
#pragma unroll
            for (int ns = 0; ns < 4; ns++) {
                int j8 = 4 * wn + ns;
                uint2 bH = FH[gidx(q, k16, j8, lane)];
                uint2 bL = FL[gidx(q, k16, j8, lane)];
#pragma unroll
                for (int ms = 0; ms < 2; ms++) {
                    mma_bf16(acc[ms][ns], aH[ms][0], aH[ms][1], bH);  // hi*hi
                    mma_bf16(acc[ms][ns], aH[ms][0], aH[ms][1], bL);  // hi*lo
                    mma_bf16(acc[ms][ns], aL[ms][0], aL[ms][1], bH);  // lo*hi
                }
            }
        }
        // store (C - 1) fragments: c0,c1 -> (row g, col 2tc..), c2,c3 -> row+8
#pragma unroll
        for (int ms = 0; ms < 2; ms++) {
            int row0 = 64 * h + 32 * wm + 16 * ms + g8;
#pragma unroll
            for (int ns = 0; ns < 4; ns++) {
                int col = 32 * wn + 8 * ns + 2 * tc;
                *(float2*)&sM[row0 * M_STRIDE + col] =
                    make_float2(acc[ms][ns][0] - 1.0f, acc[ms][ns][1] - 1.0f);
                *(float2*)&sM[(row0 + 8) * M_STRIDE + col] =
                    make_float2(acc[ms][ns][2] - 1.0f, acc[ms][ns][3] - 1.0f);
            }
        }
    }
    __syncthreads();   // M' complete and visible to warp 0

    // --- Phase 2: single-warp wavefront PDE, register-resident ---
    // K[i][j] = K[i][j-1] + K[i-1][j] + K[i-1][j-1] * M'[i-1][j-1]
    // Lane L owns rows i = 4L+1 .. 4L+4.  vp[r] = K at step dg-1, vp2[r] at
    // dg-2 for owned row r.  M' address for row i at step dg:
    //   (i-1)*M_STRIDE + (dg - i - 1)  =  base[r] + dg   (always in-bounds).
    if (wid == 0) {
        float vp[4], vp2[4];
        int base[4], irow[4];
#pragma unroll
        for (int r = 0; r < 4; r++) {
            vp[r] = 1.0f; vp2[r] = 1.0f;
            int i = 4 * lane + r + 1;
            irow[r] = i;
            base[r] = (i - 1) * M_STRIDE - i - 1;
        }

        // dg in [2,128]: every active cell has j = dg-i in [1,127] automatically;
        // cells with dg <= i are left/bottom boundary -> value 1.
#pragma unroll 4
        for (int dg = 2; dg <= 128; dg++) {
            float up  = __shfl_up_sync(0xffffffffu, vp[3], 1);
            float up2 = __shfl_up_sync(0xffffffffu, vp2[3], 1);
            if (lane == 0) { up = 1.0f; up2 = 1.0f; }   // row 0 boundary = 1
            float nv[4];
#pragma unroll
            for (int r = 0; r < 4; r++) {
                float m  = sM[base[r] + dg];
                float u  = (r == 0) ? up  : vp[r - 1];
                float u2 = (r == 0) ? up2 : vp2[r - 1];
                float comp = fmaf(u2, m, vp[r] + u);
                nv[r] = (dg <= irow[r]) ? 1.0f : comp;
            }
#pragma unroll
            for (int r = 0; r < 4; r++) { vp2[r] = vp[r]; vp[r] = nv[r]; }
        }

        // dg in [129,254]: all rows started; rows finish when dg-i > 127 (hold).
#pragma unroll 4
        for (int dg = 129; dg <= 254; dg++) {
            float up  = __shfl_up_sync(0xffffffffu, vp[3], 1);
            float up2 = __shfl_up_sync(0xffffffffu, vp2[3], 1);
            if (lane == 0) { up = 1.0f; up2 = 1.0f; }
            float nv[4];
#pragma unroll
            for (int r = 0; r < 4; r++) {
                float m  = sM[base[r] + dg];
                float u  = (r == 0) ? up  : vp[r - 1];
                float u2 = (r == 0) ? up2 : vp2[r - 1];
                float comp = fmaf(u2, m, vp[r] + u);
                nv[r] = (dg - irow[r] <= 127) ? comp : vp[r];
            }
#pragma unroll
            for (int r = 0; r < 4; r++) { vp2[r] = vp[r]; vp[r] = nv[r]; }
        }

        // K[127][127] lives on lane 31, r = 2 (i = 127), computed at dg = 254.
        if (lane == 31) g_res[job] = w * vp[2];
    }
}

// ---------------------------------------------------------------------------
// Deterministic reduction: mmd = mean(KXX) + mean(KYY) - 2*mean(KXY)
// ---------------------------------------------------------------------------
__global__ void sig_finalize_kernel(float* __restrict__ out) {
    __shared__ double sh0[256], sh1[256], sh2[256];
    int tid = threadIdx.x;
    double xx = 0.0, yy = 0.0, xy = 0.0;
    for (int idx = tid; idx < NJOBS; idx += 256) {
        double v = (double)g_res[idx];
        if (idx < NTRI) xx += v;
        else if (idx < 2 * NTRI) yy += v;
        else xy += v;
    }
    sh0[tid] = xx; sh1[tid] = yy; sh2[tid] = xy;
    __syncthreads();
    for (int s = 128; s > 0; s >>= 1) {
        if (tid < s) {
            sh0[tid] += sh0[tid + s];
            sh1[tid] += sh1[tid + s];
            sh2[tid] += sh2[tid + s];
        }
        __syncthreads();
    }
    if (tid == 0) {
        double m = sh0[0] / 4096.0 + sh1[0] / 4096.0 - 2.0 * sh2[0] / 4096.0;
        out[0] = (float)m;
    }
}

// ---------------------------------------------------------------------------
extern "C" void kernel_launch(void* const* d_in, const int* in_sizes, int n_in,
                              void* d_out, int out_size) {
    (void)in_sizes; (void)n_in; (void)out_size;
    const float* X = (const float*)d_in[0];
    const float* Y = (const float*)d_in[1];
    float* out = (float*)d_out;

    cudaFuncSetAttribute(sig_pair_kernel,
                         cudaFuncAttributeMaxDynamicSharedMemorySize, SMEM_DYN);

    const int ngr = NPATH * GR_PER_PATH;
    sig_prep_kernel<<<(ngr + 255) / 256, 256>>>(X, Y);
    sig_pair_kernel<<<NJOBS, 256, SMEM_DYN>>>();
    sig_finalize_kernel<<<1, 256>>>(out);
}

// round 13
// speedup vs baseline: 2.5933x; 1.0797x over previous
#include <cuda_runtime.h>
#include <cuda_bf16.h>
#include <cstdint>

// ---------------------------------------------------------------------------
// Problem constants
// ---------------------------------------------------------------------------
#define A_N 64          // batch per set
#define T_N 128         // time steps
#define D_N 128         // feature dim
#define MM  127         // increments per path
#define NTRI 2080       // 64*65/2 upper-triangle pairs
#define NJOBS 8256      // 2080 (XX) + 2080 (YY) + 4096 (XY)
#define NPATH 128       // 64 X paths + 64 Y paths

// Fragment-permuted storage: per path 8 k16-chunks x 16 r8-groups x 32 lanes
// x 2 subs x 4B  = 32KB  (8192 uint32 granules per path)
#define GR_PER_PATH 8192
#define HALF_U32   4096                // uint32 granules per K-half (k16 0-3 / 4-7)

// Smem: one 64KB buffer with two lives:
//   Life 1 (GEMM): 4 fragment K-HALF tiles of 16KB: [AH][AL][BH][BL]
//                  (K is staged in two halves; tiles are reloaded per half)
//   Life 2 (PDE):  M' = (M-1) matrix, 128 x 128 floats
#define TILE_U2   2048                 // uint2 granules per 16KB half-tile
#define M_STRIDE  128
#define SMEM_DYN  (64 * 1024)

// ---------------------------------------------------------------------------
// Scratch (static __device__ arrays: allocation-free per harness rules)
// ---------------------------------------------------------------------------
__device__ __align__(16) unsigned int g_fragH[NPATH * GR_PER_PATH];  // bf16 hi
__device__ __align__(16) unsigned int g_fragL[NPATH * GR_PER_PATH];  // bf16 lo
__device__ float g_res[NJOBS];

// ---------------------------------------------------------------------------
// Warp mma: m16n8k16 row.col f32.bf16.bf16.f32  (HMMA, legal at compute_103)
// ---------------------------------------------------------------------------
__device__ __forceinline__ void mma_bf16(float* d, uint2 a0, uint2 a1, uint2 b) {
    asm volatile(
        "mma.sync.aligned.m16n8k16.row.col.f32.bf16.bf16.f32 "
        "{%0,%1,%2,%3}, {%4,%5,%6,%7}, {%8,%9}, {%0,%1,%2,%3};"
        : "+f"(d[0]), "+f"(d[1]), "+f"(d[2]), "+f"(d[3])
        : "r"(a0.x), "r"(a1.x), "r"(a0.y), "r"(a1.y), "r"(b.x), "r"(b.y));
}

// granule-pair index within one K-HALF tile (uint2 units), kk = k16 within half
__device__ __forceinline__ int tidx(int kk, int r8, int lane) {
    return (kk * 16 + r8) * 32 + lane;      // max (3*16+15)*32+31 = 2047 < TILE_U2
}

// ---------------------------------------------------------------------------
// Prologue: increments dZ = Z[:,1:]-Z[:,:-1] (row 127 zero-padded), split
// into bf16 hi + bf16 lo, stored directly in mma-fragment-permuted layout.
// ---------------------------------------------------------------------------
__global__ void sig_prep_kernel(const float* __restrict__ X,
                                const float* __restrict__ Y) {
    int t = blockIdx.x * blockDim.x + threadIdx.x;
    if (t >= NPATH * GR_PER_PATH) return;
    int path = t >> 13;                 // /8192
    int rem  = t & 8191;
    int k16  = rem >> 10;
    int rem2 = rem & 1023;
    int r8   = rem2 >> 6;
    int rem3 = rem2 & 63;
    int lane = rem3 >> 1;
    int sub  = rem3 & 1;
    int g  = lane >> 2;
    int tc = lane & 3;
    int r  = r8 * 8 + g;
    int k  = k16 * 16 + sub * 8 + tc * 2;

    float d0 = 0.0f, d1 = 0.0f;
    if (r < MM) {
        const float* src = (path < A_N) ? (X + path * T_N * D_N)
                                        : (Y + (path - A_N) * T_N * D_N);
        const float* p0 = src + r * D_N + k;
        d0 = p0[D_N] - p0[0];
        d1 = p0[D_N + 1] - p0[1];
    }
    __nv_bfloat16 h0 = __float2bfloat16(d0);
    __nv_bfloat16 h1 = __float2bfloat16(d1);
    __nv_bfloat16 l0 = __float2bfloat16(d0 - __bfloat162float(h0));
    __nv_bfloat16 l1 = __float2bfloat16(d1 - __bfloat162float(h1));
    unsigned int hp = ((unsigned int)__bfloat16_as_ushort(h1) << 16) |
                       (unsigned int)__bfloat16_as_ushort(h0);
    unsigned int lp = ((unsigned int)__bfloat16_as_ushort(l1) << 16) |
                       (unsigned int)__bfloat16_as_ushort(l0);
    g_fragH[t] = hp;
    g_fragL[t] = lp;
}

// ---------------------------------------------------------------------------
// Main: one CTA (256 threads, 8 warps) per job.
//   For each K-half (k16 0-3, then 4-7):
//     - cooperative copy of both paths' half-tiles to smem (64KB exactly)
//     - mma.sync bf16 3-pass split GEMM from smem; 64 fp32 accumulators
//       stay register-resident across both halves
//   Then: write (M-1) over the dead tile buffer; single-warp register PDE.
//   Gmem fragment traffic per CTA: 128KB (vs 512KB when reading direct).
// ---------------------------------------------------------------------------
__global__ __launch_bounds__(256, 2) void sig_pair_kernel() {
    extern __shared__ float smem[];
    float* sM = smem;
    uint2* sAH = (uint2*)smem;
    uint2* sAL = sAH + TILE_U2;
    uint2* sBH = sAL + TILE_U2;
    uint2* sBL = sBH + TILE_U2;

    const int job = blockIdx.x;
    const int tid = threadIdx.x;
    const int lane = tid & 31;
    const int wid = tid >> 5;
    const int wm = wid >> 2;    // 0..1 (m-block within half)
    const int wn = wid & 3;     // 0..3 (n-block)

    // --- decode job -> (p, q path indices, weight) ---
    int p, q;
    float w = 1.0f;
    if (job < 2 * NTRI) {
        bool isY = job >= NTRI;
        int t = isY ? job - NTRI : job;
        int a = 0, rl = A_N;
        while (t >= rl) { t -= rl; rl--; a++; }
        int b = a + t;
        int off = isY ? A_N : 0;
        p = a + off;
        q = b + off;
        w = (a == b) ? 1.0f : 2.0f;     // symmetric gram: off-diag twice
    } else {
        int t = job - 2 * NTRI;
        p = (t >> 6);                   // X path
        q = A_N + (t & 63);             // Y path
    }

    const int g8 = lane >> 2;
    const int tc = lane & 3;
    float acc[2][2][4][4];              // [half][ms][ns][c]
#pragma unroll
    for (int h = 0; h < 2; h++)
#pragma unroll
        for (int ms = 0; ms < 2; ms++)
#pragma unroll
            for (int ns = 0; ns < 4; ns++)
#pragma unroll
                for (int c = 0; c < 4; c++) acc[h][ms][ns][c] = 0.0f;

#pragma unroll
    for (int kh = 0; kh < 2; kh++) {
        // --- stage this K-half's tiles (each a contiguous 16KB gmem block) ---
        {
            const uint4* gAH = (const uint4*)(g_fragH + p * GR_PER_PATH + kh * HALF_U32);
            const uint4* gAL = (const uint4*)(g_fragL + p * GR_PER_PATH + kh * HALF_U32);
            const uint4* gBH = (const uint4*)(g_fragH + q * GR_PER_PATH + kh * HALF_U32);
            const uint4* gBL = (const uint4*)(g_fragL + q * GR_PER_PATH + kh * HALF_U32);
            uint4* dAH = (uint4*)sAH;
            uint4* dAL = (uint4*)sAL;
            uint4* dBH = (uint4*)sBH;
            uint4* dBL = (uint4*)sBL;
#pragma unroll
            for (int it = 0; it < 4; it++) {
                int i = it * 256 + tid;     // 1024 uint4 per 16KB half-tile
                dAH[i] = gAH[i];
                dAL[i] = gAL[i];
                dBH[i] = gBH[i];
                dBL[i] = gBL[i];
            }
        }
        __syncthreads();

        // --- GEMM over this half's 4 k16 steps ---
#pragma unroll
        for (int h = 0; h < 2; h++) {
            const int r8base = 8 * h + 4 * wm;
#pragma unroll
            for (int kk = 0; kk < 4; kk++) {
                uint2 aH[2][2], aL[2][2];
#pragma unroll
                for (int ms = 0; ms < 2; ms++) {
                    int r8 = r8base + 2 * ms;
                    aH[ms][0] = sAH[tidx(kk, r8, lane)];
                    aH[ms][1] = sAH[tidx(kk, r8 + 1, lane)];
                    aL[ms][0] = sAL[tidx(kk, r8, lane)];
                    aL[ms][1] = sAL[tidx(kk, r8 + 1, lane)];
                }
#pragma unroll
                for (int ns = 0; ns < 4; ns++) {
                    int j8 = 4 * wn + ns;
                    uint2 bH = sBH[tidx(kk, j8, lane)];
                    uint2 bL = sBL[tidx(kk, j8, lane)];
#pragma unroll
                    for (int ms = 0; ms < 2; ms++) {
                        mma_bf16(acc[h][ms][ns], aH[ms][0], aH[ms][1], bH);  // hi*hi
                        mma_bf16(acc[h][ms][ns], aH[ms][0], aH[ms][1], bL);  // hi*lo
                        mma_bf16(acc[h][ms][ns], aL[ms][0], aL[ms][1], bH);  // lo*hi
                    }
                }
            }
        }
        __syncthreads();   // all reads of this half done before restage/M write
    }

    // --- write (M - 1) over the dead tile buffer ---
#pragma unroll
    for (int h = 0; h < 2; h++)
#pragma unroll
        for (int ms = 0; ms < 2; ms++) {
            int row0 = 64 * h + 32 * wm + 16 * ms + g8;
#pragma unroll
            for (int ns = 0; ns < 4; ns++) {
                int col = 32 * wn + 8 * ns + 2 * tc;
                *(float2*)&sM[row0 * M_STRIDE + col] =
                    make_float2(acc[h][ms][ns][0] - 1.0f, acc[h][ms][ns][1] - 1.0f);
                *(float2*)&sM[(row0 + 8) * M_STRIDE + col] =
                    make_float2(acc[h][ms][ns][2] - 1.0f, acc[h][ms][ns][3] - 1.0f);
            }
        }
    __syncthreads();   // M' complete and visible to warp 0

    // --- single-warp wavefront PDE, register-resident ---
    // K[i][j] = K[i][j-1] + K[i-1][j] + K[i-1][j-1] * M'[i-1][j-1]
    // Lane L owns rows i = 4L+1 .. 4L+4.  M' address for row i at step dg:
    //   (i-1)*M_STRIDE + (dg-i-1) = base[r] + dg  (always in-bounds).
    if (wid == 0) {
        float vp[4], vp2[4];
        int base[4], irow[4];
#pragma unroll
        for (int r = 0; r < 4; r++) {
            vp[r] = 1.0f; vp2[r] = 1.0f;
            int i = 4 * lane + r + 1;
            irow[r] = i;
            base[r] = (i - 1) * M_STRIDE - i - 1;
        }

        // dg in [2,128]: cells with dg <= i are boundary -> value 1.
#pragma unroll 4
        for (int dg = 2; dg <= 128; dg++) {
            float up  = __shfl_up_sync(0xffffffffu, vp[3], 1);
            float up2 = __shfl_up_sync(0xffffffffu, vp2[3], 1);
            if (lane == 0) { up = 1.0f; up2 = 1.0f; }   // row 0 boundary
            float nv[4];
#pragma unroll
            for (int r = 0; r < 4; r++) {
                float m  = sM[base[r] + dg];
                float u  = (r == 0) ? up  : vp[r - 1];
                float u2 = (r == 0) ? up2 : vp2[r - 1];
                float comp = fmaf(u2, m, vp[r] + u);
                nv[r] = (dg <= irow[r]) ? 1.0f : comp;
            }
#pragma unroll
            for (int r = 0; r < 4; r++) { vp2[r] = vp[r]; vp[r] = nv[r]; }
        }

        // dg in [129,254]: rows finish when dg-i > 127 (hold value).
#pragma unroll 4
        for (int dg = 129; dg <= 254; dg++) {
            float up  = __shfl_up_sync(0xffffffffu, vp[3], 1);
            float up2 = __shfl_up_sync(0xffffffffu, vp2[3], 1);
            if (lane == 0) { up = 1.0f; up2 = 1.0f; }
            float nv[4];
#pragma unroll
            for (int r = 0; r < 4; r++) {
                float m  = sM[base[r] + dg];
                float u  = (r == 0) ? up  : vp[r - 1];
                float u2 = (r == 0) ? up2 : vp2[r - 1];
                float comp = fmaf(u2, m, vp[r] + u);
                nv[r] = (dg - irow[r] <= 127) ? comp : vp[r];
            }
#pragma unroll
            for (int r = 0; r < 4; r++) { vp2[r] = vp[r]; vp[r] = nv[r]; }
        }

        // K[127][127] lives on lane 31, r = 2 (i = 127).
        if (lane == 31) g_res[job] = w * vp[2];
    }
}

// ---------------------------------------------------------------------------
// Deterministic reduction: mmd = mean(KXX) + mean(KYY) - 2*mean(KXY)
// ---------------------------------------------------------------------------
__global__ void sig_finalize_kernel(float* __restrict__ out) {
    __shared__ double sh0[256], sh1[256], sh2[256];
    int tid = threadIdx.x;
    double xx = 0.0, yy = 0.0, xy = 0.0;
    for (int idx = tid; idx < NJOBS; idx += 256) {
        double v = (double)g_res[idx];
        if (idx < NTRI) xx += v;
        else if (idx < 2 * NTRI) yy += v;
        else xy += v;
    }
    sh0[tid] = xx; sh1[tid] = yy; sh2[tid] = xy;
    __syncthreads();
    for (int s = 128; s > 0; s >>= 1) {
        if (tid < s) {
            sh0[tid] += sh0[tid + s];
            sh1[tid] += sh1[tid + s];
            sh2[tid] += sh2[tid + s];
        }
        __syncthreads();
    }
    if (tid == 0) {
        double m = sh0[0] / 4096.0 + sh1[0] / 4096.0 - 2.0 * sh2[0] / 4096.0;
        out[0] = (float)m;
    }
}

// ---------------------------------------------------------------------------
extern "C" void kernel_launch(void* const* d_in, const int* in_sizes, int n_in,
                              void* d_out, int out_size) {
    (void)in_sizes; (void)n_in; (void)out_size;
    const float* X = (const float*)d_in[0];
    const float* Y = (const float*)d_in[1];
    float* out = (float*)d_out;

    cudaFuncSetAttribute(sig_pair_kernel,
                         cudaFuncAttributeMaxDynamicSharedMemorySize, SMEM_DYN);

    const int ngr = NPATH * GR_PER_PATH;
    sig_prep_kernel<<<(ngr + 255) / 256, 256>>>(X, Y);
    sig_pair_kernel<<<NJOBS, 256, SMEM_DYN>>>();
    sig_finalize_kernel<<<1, 256>>>(out);
}